// round 1
// baseline (speedup 1.0000x reference)
#include <cuda_runtime.h>
#include <cstdint>

#define NN 20000
#define DD 32
#define HH 64

typedef unsigned long long ull;

// ---------------- scratch (static device globals; no allocation) ----------------
__device__ int   g_nbr_sorted[NN * DD];            // 2.56 MB
__device__ float g_Xg[(size_t)NN * 256];           // 20.5 MB (precomputed input gates)
__device__ float g_hA[(size_t)NN * HH];            // 5.12 MB
__device__ float g_hB[(size_t)NN * HH];            // 5.12 MB
__device__ float g_agg[(size_t)NN * HH];           // 5.12 MB
__device__ float g_WT[64 * 256];                   // transposed W_hh: g_WT[k*256 + r] = W_hh[r*64 + k]

// ---------------- helpers ----------------
__device__ __forceinline__ ull fma2(ull a, ull b, ull c) {
    ull d;
    asm("fma.rn.f32x2 %0, %1, %2, %3;" : "=l"(d) : "l"(a), "l"(b), "l"(c));
    return d;
}
__device__ __forceinline__ ull pack2(float lo, float hi) {
    ull r; asm("mov.b64 %0, {%1, %2};" : "=l"(r) : "f"(lo), "f"(hi)); return r;
}
__device__ __forceinline__ float2 unpack2(ull v) {
    float2 r; asm("mov.b64 {%0, %1}, %2;" : "=f"(r.x), "=f"(r.y) : "l"(v)); return r;
}
__device__ __forceinline__ float sigf(float x) { return 1.0f / (1.0f + __expf(-x)); }
__device__ __forceinline__ float tanhf_(float x) { return 2.0f / (1.0f + __expf(-2.0f * x)) - 1.0f; }

// ---------------- neighbor sort: warp-per-node bitonic over 32 lanes ----------------
__global__ void sort_kernel(const int* __restrict__ nbr) {
    int gw = (blockIdx.x * blockDim.x + threadIdx.x) >> 5;
    int lane = threadIdx.x & 31;
    if (gw >= NN) return;
    int v = nbr[gw * DD + lane];
#pragma unroll
    for (int k = 2; k <= 32; k <<= 1) {
#pragma unroll
        for (int j = k >> 1; j > 0; j >>= 1) {
            int p = __shfl_xor_sync(0xFFFFFFFFu, v, j);
            bool up = ((lane & k) == 0);
            bool lo = ((lane & j) == 0);
            int mn = min(v, p), mx = max(v, p);
            v = (up == lo) ? mn : mx;
        }
    }
    g_nbr_sorted[gw * DD + lane] = v;
}

// ---------------- W_hh transpose to global (coalesced consumption in lstm) ----------------
__global__ void transpose_whh(const float* __restrict__ W) {
    int k = blockIdx.x;  // 0..63
    for (int r = threadIdx.x; r < 256; r += blockDim.x)
        g_WT[k * 256 + r] = W[r * 64 + k];
}

// ---------------- input-gate projection: Xg = h_in @ W_ih.T + (b_ih + b_hh) ----------------
#define PROJ_SMEM (64 * 257 * 4 + 8 * 64 * 4)
__global__ void proj_kernel(const float* __restrict__ h_in, const float* __restrict__ W_ih,
                            const float* __restrict__ b_ih, const float* __restrict__ b_hh,
                            int in_d) {
    extern __shared__ float sm[];
    float* sWT = sm;              // sWT[k*257 + j], j<256 (padded stride: conflict-free)
    float* sh  = sm + 64 * 257;   // 8 nodes x in_d
    int tid = threadIdx.x;
    for (int i = tid; i < in_d * 256; i += 256) {
        int j = i / in_d, k = i - j * in_d;
        sWT[k * 257 + j] = W_ih[i];          // coalesced global read
    }
    int base = blockIdx.x * 8;
    for (int i = tid; i < 8 * in_d; i += 256) sh[i] = h_in[(size_t)base * in_d + i];
    float bias = b_ih[tid] + b_hh[tid];
    __syncthreads();
#pragma unroll
    for (int m = 0; m < 8; m++) {
        float acc = bias;
        for (int k = 0; k < in_d; k++) acc = fmaf(sh[m * in_d + k], sWT[k * 257 + tid], acc);
        g_Xg[(size_t)(base + m) * 256 + tid] = acc;
    }
}

// ---------------- LSTM recurrence: warp handles 4 nodes, f32x2 packed math ----------------
#define LSTM_SMEM (64 * 128 * 8 + 8 * 4 * 64 * 8)   // 64KB W(packed) + 16KB h(dup-packed)
__global__ __launch_bounds__(256, 2) void lstm_kernel() {
    extern __shared__ char smem[];
    ull* sW  = (ull*)smem;                      // sW[k*128 + g*32 + lane] = (W_hh[row][k], W_hh[row+1][k])
    ull* h2s = (ull*)(smem + 64 * 128 * 8);     // [8 warps][4 nodes][64] duplicated-pair h
    int tid = threadIdx.x, lane = tid & 31, w = tid >> 5;

    const ull* gWT = (const ull*)g_WT;
    for (int i = tid; i < 64 * 128; i += 256) sW[i] = gWT[i];   // coalesced 8B copies

    ull* myh = h2s + (w * 4) * 64;
#pragma unroll
    for (int m = 0; m < 4; m++) {
        myh[m * 64 + lane] = 0ull;
        myh[m * 64 + lane + 32] = 0ull;
    }
    __syncthreads();

    int nodeb = blockIdx.x * 32 + w * 4;
    float c[4][2], hl[4][2];
#pragma unroll
    for (int m = 0; m < 4; m++) { c[m][0] = c[m][1] = 0.f; hl[m][0] = hl[m][1] = 0.f; }

    int idxs[4];
#pragma unroll
    for (int m = 0; m < 4; m++) idxs[m] = g_nbr_sorted[(nodeb + m) * DD];

    for (int t = 0; t < DD; t++) {
        // gather precomputed input gates for this step (hide latency behind k-loop)
        float2 xg[4][4];
#pragma unroll
        for (int m = 0; m < 4; m++) {
            const float2* xp = (const float2*)(g_Xg + (size_t)idxs[m] * 256);
#pragma unroll
            for (int g = 0; g < 4; g++) xg[m][g] = __ldg(&xp[g * 32 + lane]);
        }
        // prefetch next step's neighbor ids
        int tn = (t + 1) & 31;
        int idxn[4];
#pragma unroll
        for (int m = 0; m < 4; m++) idxn[m] = g_nbr_sorted[(nodeb + m) * DD + tn];

        ull acc[4][4];
#pragma unroll
        for (int m = 0; m < 4; m++)
#pragma unroll
            for (int g = 0; g < 4; g++) acc[m][g] = 0ull;   // bits 0 == (0.f, 0.f)

#pragma unroll 8
        for (int k = 0; k < 64; k++) {
            ull wv[4], hv[4];
#pragma unroll
            for (int g = 0; g < 4; g++) wv[g] = sW[k * 128 + g * 32 + lane];
#pragma unroll
            for (int m = 0; m < 4; m++) hv[m] = myh[m * 64 + k];
#pragma unroll
            for (int m = 0; m < 4; m++)
#pragma unroll
                for (int g = 0; g < 4; g++)
                    acc[m][g] = fma2(wv[g], hv[m], acc[m][g]);
        }
        __syncwarp();
#pragma unroll
        for (int m = 0; m < 4; m++) {
            float2 gi = unpack2(acc[m][0]);
            float2 gf = unpack2(acc[m][1]);
            float2 gg = unpack2(acc[m][2]);
            float2 go = unpack2(acc[m][3]);
            gi.x += xg[m][0].x; gi.y += xg[m][0].y;
            gf.x += xg[m][1].x; gf.y += xg[m][1].y;
            gg.x += xg[m][2].x; gg.y += xg[m][2].y;
            go.x += xg[m][3].x; go.y += xg[m][3].y;
            float I0 = sigf(gi.x), F0 = sigf(gf.x), G0 = tanhf_(gg.x), O0 = sigf(go.x);
            float I1 = sigf(gi.y), F1 = sigf(gf.y), G1 = tanhf_(gg.y), O1 = sigf(go.y);
            c[m][0] = F0 * c[m][0] + I0 * G0;
            c[m][1] = F1 * c[m][1] + I1 * G1;
            float h0 = O0 * tanhf_(c[m][0]);
            float h1 = O1 * tanhf_(c[m][1]);
            hl[m][0] = h0; hl[m][1] = h1;
            myh[m * 64 + 2 * lane]     = pack2(h0, h0);
            myh[m * 64 + 2 * lane + 1] = pack2(h1, h1);
        }
        __syncwarp();
#pragma unroll
        for (int m = 0; m < 4; m++) idxs[m] = idxn[m];
    }
#pragma unroll
    for (int m = 0; m < 4; m++) {
        float2 v = make_float2(hl[m][0], hl[m][1]);
        *(float2*)(g_agg + (size_t)(nodeb + m) * 64 + 2 * lane) = v;
    }
}

// ---------------- layer combine: h_out = relu([h_in, agg] @ Wl.T + bl) ----------------
__global__ void combine_kernel(const float* __restrict__ h_in, const float* __restrict__ Wl,
                               const float* __restrict__ bl, int in_d, float* __restrict__ h_out) {
    __shared__ float sWT[128 * 65];     // sWT[k*65 + j], k < in_d+64, j < 64
    __shared__ float scomb[4][128];
    int K = in_d + 64;
    int tid = threadIdx.x;
    for (int i = tid; i < 64 * K; i += 256) {
        int j = i / K, k = i - j * K;
        sWT[k * 65 + j] = Wl[i];
    }
    int base = blockIdx.x * 4;
    for (int i = tid; i < 4 * in_d; i += 256) {
        int m = i / in_d;
        scomb[m][i - m * in_d] = h_in[(size_t)base * in_d + i];
    }
    for (int i = tid; i < 4 * 64; i += 256)
        scomb[i >> 6][in_d + (i & 63)] = g_agg[(size_t)base * 64 + i];
    __syncthreads();
    int m = tid >> 6, j = tid & 63;
    float acc = bl[j];
    for (int k = 0; k < K; k++) acc = fmaf(scomb[m][k], sWT[k * 65 + j], acc);
    h_out[(size_t)(base + m) * 64 + j] = fmaxf(acc, 0.f);
}

// ---------------- output head ----------------
__global__ void out_kernel(const float* __restrict__ h, const float* __restrict__ W_out,
                           const float* __restrict__ b_out, float* __restrict__ out) {
    int gw = (blockIdx.x * blockDim.x + threadIdx.x) >> 5;
    int lane = threadIdx.x & 31;
    if (gw >= NN) return;
    float2 hv = *(const float2*)(h + (size_t)gw * 64 + 2 * lane);
    float2 wv = *(const float2*)(W_out + 2 * lane);
    float s = hv.x * wv.x + hv.y * wv.y;
#pragma unroll
    for (int o = 16; o; o >>= 1) s += __shfl_xor_sync(0xFFFFFFFFu, s, o);
    if (lane == 0) out[gw] = s + b_out[0];
}

// ---------------- launch ----------------
extern "C" void kernel_launch(void* const* d_in, const int* in_sizes, int n_in,
                              void* d_out, int out_size) {
    (void)in_sizes; (void)n_in; (void)out_size;
    const float* nf   = (const float*)d_in[0];
    const int*   nbr  = (const int*)d_in[1];
    const float* Wout = (const float*)d_in[20];
    const float* bout = (const float*)d_in[21];
    float* out = (float*)d_out;

    float *hA = nullptr, *hB = nullptr;
    cudaGetSymbolAddress((void**)&hA, g_hA);
    cudaGetSymbolAddress((void**)&hB, g_hB);

    cudaFuncSetAttribute(lstm_kernel, cudaFuncAttributeMaxDynamicSharedMemorySize, LSTM_SMEM);
    cudaFuncSetAttribute(proj_kernel, cudaFuncAttributeMaxDynamicSharedMemorySize, PROJ_SMEM);

    sort_kernel<<<NN / 8, 256>>>(nbr);

    const float* h_in = nf;
    float* houts[3] = { hA, hB, hA };
    for (int l = 0; l < 3; l++) {
        const float* W_ih = (const float*)d_in[2 + 6 * l + 0];
        const float* W_hh = (const float*)d_in[2 + 6 * l + 1];
        const float* b_ih = (const float*)d_in[2 + 6 * l + 2];
        const float* b_hh = (const float*)d_in[2 + 6 * l + 3];
        const float* Wl   = (const float*)d_in[2 + 6 * l + 4];
        const float* bl   = (const float*)d_in[2 + 6 * l + 5];
        int in_d = (l == 0) ? 3 : 64;

        proj_kernel<<<NN / 8, 256, PROJ_SMEM>>>(h_in, W_ih, b_ih, b_hh, in_d);
        transpose_whh<<<64, 256>>>(W_hh);
        lstm_kernel<<<NN / 32, 256, LSTM_SMEM>>>();
        combine_kernel<<<NN / 4, 256>>>(h_in, Wl, bl, in_d, houts[l]);
        h_in = houts[l];
    }
    out_kernel<<<NN / 8, 256>>>(h_in, Wout, bout, out);
}

// round 2
// speedup vs baseline: 1.2456x; 1.2456x over previous
#include <cuda_runtime.h>
#include <cstdint>

#define NN 20000
#define DD 32
#define HH 64

typedef unsigned long long ull;

// ---------------- scratch (static device globals; no allocation) ----------------
__device__ int   g_nbr_sorted[NN * DD];
__device__ float g_Xg[(size_t)NN * 256];
__device__ float g_hA[(size_t)NN * HH];
__device__ float g_hB[(size_t)NN * HH];
__device__ float g_agg[(size_t)NN * HH];
__device__ float g_WT[64 * 256];   // g_WT[k*256 + r] = W_hh[r*64 + k]

// ---------------- helpers ----------------
__device__ __forceinline__ ull fma2(ull a, ull b, ull c) {
    ull d;
    asm("fma.rn.f32x2 %0, %1, %2, %3;" : "=l"(d) : "l"(a), "l"(b), "l"(c));
    return d;
}
__device__ __forceinline__ ull pack2(float lo, float hi) {
    ull r; asm("mov.b64 %0, {%1, %2};" : "=l"(r) : "f"(lo), "f"(hi)); return r;
}
__device__ __forceinline__ float2 unpack2(ull v) {
    float2 r; asm("mov.b64 {%0, %1}, %2;" : "=f"(r.x), "=f"(r.y) : "l"(v)); return r;
}
__device__ __forceinline__ float tanha(float x) {
    float r; asm("tanh.approx.f32 %0, %1;" : "=f"(r) : "f"(x)); return r;
}
__device__ __forceinline__ float sigta(float x) {
    return fmaf(tanha(0.5f * x), 0.5f, 0.5f);
}

// ---------------- neighbor sort: warp-per-node bitonic over 32 lanes ----------------
__global__ void sort_kernel(const int* __restrict__ nbr) {
    int gw = (blockIdx.x * blockDim.x + threadIdx.x) >> 5;
    int lane = threadIdx.x & 31;
    if (gw >= NN) return;
    int v = nbr[gw * DD + lane];
#pragma unroll
    for (int k = 2; k <= 32; k <<= 1) {
#pragma unroll
        for (int j = k >> 1; j > 0; j >>= 1) {
            int p = __shfl_xor_sync(0xFFFFFFFFu, v, j);
            bool up = ((lane & k) == 0);
            bool lo = ((lane & j) == 0);
            int mn = min(v, p), mx = max(v, p);
            v = (up == lo) ? mn : mx;
        }
    }
    g_nbr_sorted[gw * DD + lane] = v;
}

// ---------------- W_hh transpose ----------------
__global__ void transpose_whh(const float* __restrict__ W) {
    int k = blockIdx.x;
    for (int r = threadIdx.x; r < 256; r += blockDim.x)
        g_WT[k * 256 + r] = W[r * 64 + k];
}

// ---------------- Xg = h_in @ W_ih.T + (b_ih + b_hh) ----------------
#define PROJ_SMEM (64 * 257 * 4 + 8 * 64 * 4)
__global__ void proj_kernel(const float* __restrict__ h_in, const float* __restrict__ W_ih,
                            const float* __restrict__ b_ih, const float* __restrict__ b_hh,
                            int in_d) {
    extern __shared__ float sm[];
    float* sWT = sm;
    float* sh  = sm + 64 * 257;
    int tid = threadIdx.x;
    for (int i = tid; i < in_d * 256; i += 256) {
        int j = i / in_d, k = i - j * in_d;
        sWT[k * 257 + j] = W_ih[i];
    }
    int base = blockIdx.x * 8;
    for (int i = tid; i < 8 * in_d; i += 256) sh[i] = h_in[(size_t)base * in_d + i];
    float bias = b_ih[tid] + b_hh[tid];
    __syncthreads();
#pragma unroll
    for (int m = 0; m < 8; m++) {
        float acc = bias;
        for (int k = 0; k < in_d; k++) acc = fmaf(sh[m * in_d + k], sWT[k * 257 + tid], acc);
        g_Xg[(size_t)(base + m) * 256 + tid] = acc;
    }
}

// ---------------- LSTM recurrence: 4 warps/CTA, 6 nodes/warp, f32x2 packed ----------------
#define NPW 6
#define NWARP 4
#define NPC (NPW * NWARP)                           // 24 nodes per CTA
#define LSTM_SMEM (64 * 128 * 8 + NWARP * NPW * 64 * 8)   // 64KB W + 12KB h

__global__ __launch_bounds__(128) void lstm_kernel() {
    extern __shared__ char smem[];
    ull* sW  = (ull*)smem;                           // sW[k*128 + g*32 + lane]
    ull* h2s = (ull*)(smem + 64 * 128 * 8);          // [warp][node][64] duplicated pairs
    int tid = threadIdx.x, lane = tid & 31, w = tid >> 5;

    const ull* gWT = (const ull*)g_WT;
    for (int i = tid; i < 64 * 128; i += 128) sW[i] = gWT[i];

    ull* myh = h2s + (size_t)w * NPW * 64;
#pragma unroll
    for (int m = 0; m < NPW; m++) {
        myh[m * 64 + lane] = 0ull;
        myh[m * 64 + lane + 32] = 0ull;
    }
    __syncthreads();

    int nodeb = blockIdx.x * NPC + w * NPW;
    float c[NPW][2], hl[NPW][2];
#pragma unroll
    for (int m = 0; m < NPW; m++) { c[m][0] = c[m][1] = 0.f; hl[m][0] = hl[m][1] = 0.f; }

    int nclamp[NPW];
#pragma unroll
    for (int m = 0; m < NPW; m++) nclamp[m] = min(nodeb + m, NN - 1);

    int idxs[NPW];
#pragma unroll
    for (int m = 0; m < NPW; m++) idxs[m] = g_nbr_sorted[nclamp[m] * DD];

    for (int t = 0; t < DD; t++) {
        // gather precomputed input gates for this step
        float2 xg[NPW][4];
#pragma unroll
        for (int m = 0; m < NPW; m++) {
            const float2* xp = (const float2*)(g_Xg + (size_t)idxs[m] * 256);
#pragma unroll
            for (int g = 0; g < 4; g++) xg[m][g] = __ldg(&xp[g * 32 + lane]);
        }
        // prefetch next step's neighbor ids
        int tn = (t + 1) & 31;
        int idxn[NPW];
#pragma unroll
        for (int m = 0; m < NPW; m++) idxn[m] = g_nbr_sorted[nclamp[m] * DD + tn];

        ull acc[NPW][4];
#pragma unroll
        for (int m = 0; m < NPW; m++)
#pragma unroll
            for (int g = 0; g < 4; g++) acc[m][g] = 0ull;

#pragma unroll 4
        for (int k = 0; k < 64; k++) {
            ull wv[4], hv[NPW];
#pragma unroll
            for (int g = 0; g < 4; g++) wv[g] = sW[k * 128 + g * 32 + lane];
#pragma unroll
            for (int m = 0; m < NPW; m++) hv[m] = myh[m * 64 + k];
#pragma unroll
            for (int m = 0; m < NPW; m++)
#pragma unroll
                for (int g = 0; g < 4; g++)
                    acc[m][g] = fma2(wv[g], hv[m], acc[m][g]);
        }
        __syncwarp();
#pragma unroll
        for (int m = 0; m < NPW; m++) {
            float2 gi = unpack2(acc[m][0]);
            float2 gf = unpack2(acc[m][1]);
            float2 gg = unpack2(acc[m][2]);
            float2 go = unpack2(acc[m][3]);
            gi.x += xg[m][0].x; gi.y += xg[m][0].y;
            gf.x += xg[m][1].x; gf.y += xg[m][1].y;
            gg.x += xg[m][2].x; gg.y += xg[m][2].y;
            go.x += xg[m][3].x; go.y += xg[m][3].y;
            float I0 = sigta(gi.x), F0 = sigta(gf.x), G0 = tanha(gg.x), O0 = sigta(go.x);
            float I1 = sigta(gi.y), F1 = sigta(gf.y), G1 = tanha(gg.y), O1 = sigta(go.y);
            c[m][0] = F0 * c[m][0] + I0 * G0;
            c[m][1] = F1 * c[m][1] + I1 * G1;
            float h0 = O0 * tanha(c[m][0]);
            float h1 = O1 * tanha(c[m][1]);
            hl[m][0] = h0; hl[m][1] = h1;
            ulonglong2 hv2;
            hv2.x = pack2(h0, h0);
            hv2.y = pack2(h1, h1);
            *(ulonglong2*)(myh + m * 64 + 2 * lane) = hv2;     // STS.128, conflict-free
        }
        __syncwarp();
#pragma unroll
        for (int m = 0; m < NPW; m++) idxs[m] = idxn[m];
    }
#pragma unroll
    for (int m = 0; m < NPW; m++) {
        if (nodeb + m < NN) {
            float2 v = make_float2(hl[m][0], hl[m][1]);
            *(float2*)(g_agg + (size_t)(nodeb + m) * 64 + 2 * lane) = v;
        }
    }
}

// ---------------- layer combine: h_out = relu([h_in, agg] @ Wl.T + bl) ----------------
__global__ void combine_kernel(const float* __restrict__ h_in, const float* __restrict__ Wl,
                               const float* __restrict__ bl, int in_d, float* __restrict__ h_out) {
    __shared__ float sWT[128 * 65];
    __shared__ float scomb[4][128];
    int K = in_d + 64;
    int tid = threadIdx.x;
    for (int i = tid; i < 64 * K; i += 256) {
        int j = i / K, k = i - j * K;
        sWT[k * 65 + j] = Wl[i];
    }
    int base = blockIdx.x * 4;
    for (int i = tid; i < 4 * in_d; i += 256) {
        int m = i / in_d;
        scomb[m][i - m * in_d] = h_in[(size_t)base * in_d + i];
    }
    for (int i = tid; i < 4 * 64; i += 256)
        scomb[i >> 6][in_d + (i & 63)] = g_agg[(size_t)base * 64 + i];
    __syncthreads();
    int m = tid >> 6, j = tid & 63;
    float acc = bl[j];
    for (int k = 0; k < K; k++) acc = fmaf(scomb[m][k], sWT[k * 65 + j], acc);
    h_out[(size_t)(base + m) * 64 + j] = fmaxf(acc, 0.f);
}

// ---------------- output head ----------------
__global__ void out_kernel(const float* __restrict__ h, const float* __restrict__ W_out,
                           const float* __restrict__ b_out, float* __restrict__ out) {
    int gw = (blockIdx.x * blockDim.x + threadIdx.x) >> 5;
    int lane = threadIdx.x & 31;
    if (gw >= NN) return;
    float2 hv = *(const float2*)(h + (size_t)gw * 64 + 2 * lane);
    float2 wv = *(const float2*)(W_out + 2 * lane);
    float s = hv.x * wv.x + hv.y * wv.y;
#pragma unroll
    for (int o = 16; o; o >>= 1) s += __shfl_xor_sync(0xFFFFFFFFu, s, o);
    if (lane == 0) out[gw] = s + b_out[0];
}

// ---------------- launch ----------------
extern "C" void kernel_launch(void* const* d_in, const int* in_sizes, int n_in,
                              void* d_out, int out_size) {
    (void)in_sizes; (void)n_in; (void)out_size;
    const float* nf   = (const float*)d_in[0];
    const int*   nbr  = (const int*)d_in[1];
    const float* Wout = (const float*)d_in[20];
    const float* bout = (const float*)d_in[21];
    float* out = (float*)d_out;

    float *hA = nullptr, *hB = nullptr;
    cudaGetSymbolAddress((void**)&hA, g_hA);
    cudaGetSymbolAddress((void**)&hB, g_hB);

    cudaFuncSetAttribute(lstm_kernel, cudaFuncAttributeMaxDynamicSharedMemorySize, LSTM_SMEM);
    cudaFuncSetAttribute(proj_kernel, cudaFuncAttributeMaxDynamicSharedMemorySize, PROJ_SMEM);

    sort_kernel<<<NN / 8, 256>>>(nbr);

    const float* h_in = nf;
    float* houts[3] = { hA, hB, hA };
    int lstm_grid = (NN + NPC - 1) / NPC;
    for (int l = 0; l < 3; l++) {
        const float* W_ih = (const float*)d_in[2 + 6 * l + 0];
        const float* W_hh = (const float*)d_in[2 + 6 * l + 1];
        const float* b_ih = (const float*)d_in[2 + 6 * l + 2];
        const float* b_hh = (const float*)d_in[2 + 6 * l + 3];
        const float* Wl   = (const float*)d_in[2 + 6 * l + 4];
        const float* bl   = (const float*)d_in[2 + 6 * l + 5];
        int in_d = (l == 0) ? 3 : 64;

        proj_kernel<<<NN / 8, 256, PROJ_SMEM>>>(h_in, W_ih, b_ih, b_hh, in_d);
        transpose_whh<<<64, 256>>>(W_hh);
        lstm_kernel<<<lstm_grid, 128, LSTM_SMEM>>>();
        combine_kernel<<<NN / 4, 256>>>(h_in, Wl, bl, in_d, houts[l]);
        h_in = houts[l];
    }
    out_kernel<<<NN / 8, 256>>>(h_in, Wout, bout, out);
}

// round 4
// speedup vs baseline: 1.7415x; 1.3981x over previous
#include <cuda_runtime.h>
#include <cuda_bf16.h>
#include <cstdint>

#define NN 20000
#define DD 32
#define HH 64

typedef unsigned long long ull;

// ---------------- scratch (static device globals; no allocation) ----------------
__device__ int   g_nbr_sorted[NN * DD];
__device__ float g_Xg[(size_t)NN * 256];     // gate-interleaved: col = 4*u + gate
__device__ float g_hA[(size_t)NN * HH];
__device__ float g_hB[(size_t)NN * HH];
__device__ float g_agg[(size_t)NN * HH];

// ---------------- helpers ----------------
__device__ __forceinline__ uint32_t smem_u32(const void* p) {
    uint32_t a;
    asm("{ .reg .u64 t; cvta.to.shared.u64 t, %1; cvt.u32.u64 %0, t; }" : "=r"(a) : "l"(p));
    return a;
}
__device__ __forceinline__ float tanha(float x) {
    float r; asm("tanh.approx.f32 %0, %1;" : "=f"(r) : "f"(x)); return r;
}
__device__ __forceinline__ float sigta(float x) { return fmaf(tanha(0.5f * x), 0.5f, 0.5f); }

__device__ __forceinline__ void ldsm4(uint32_t* r, uint32_t a) {
    asm volatile("ldmatrix.sync.aligned.m8n8.x4.shared.b16 {%0,%1,%2,%3}, [%4];"
        : "=r"(r[0]), "=r"(r[1]), "=r"(r[2]), "=r"(r[3]) : "r"(a));
}
__device__ __forceinline__ void ldsm2(uint32_t* r, uint32_t a) {
    asm volatile("ldmatrix.sync.aligned.m8n8.x2.shared.b16 {%0,%1}, [%2];"
        : "=r"(r[0]), "=r"(r[1]) : "r"(a));
}
__device__ __forceinline__ void mma_bf16(float* d, const uint32_t* a, const uint32_t* b) {
    asm volatile("mma.sync.aligned.m16n8k16.row.col.f32.bf16.bf16.f32 "
        "{%0,%1,%2,%3}, {%4,%5,%6,%7}, {%8,%9}, {%0,%1,%2,%3};"
        : "+f"(d[0]), "+f"(d[1]), "+f"(d[2]), "+f"(d[3])
        : "r"(a[0]), "r"(a[1]), "r"(a[2]), "r"(a[3]), "r"(b[0]), "r"(b[1]));
}

// ---------------- neighbor sort ----------------
__global__ void sort_kernel(const int* __restrict__ nbr) {
    int gw = (blockIdx.x * blockDim.x + threadIdx.x) >> 5;
    int lane = threadIdx.x & 31;
    if (gw >= NN) return;
    int v = nbr[gw * DD + lane];
#pragma unroll
    for (int k = 2; k <= 32; k <<= 1) {
#pragma unroll
        for (int j = k >> 1; j > 0; j >>= 1) {
            int p = __shfl_xor_sync(0xFFFFFFFFu, v, j);
            bool up = ((lane & k) == 0);
            bool lo = ((lane & j) == 0);
            int mn = min(v, p), mx = max(v, p);
            v = (up == lo) ? mn : mx;
        }
    }
    g_nbr_sorted[gw * DD + lane] = v;
}

// ---------------- Xg = h_in @ W_ih.T + (b_ih + b_hh), gate-interleaved cols ----------------
#define PROJ_SMEM (64 * 257 * 4 + 8 * 64 * 4)
__global__ void proj_kernel(const float* __restrict__ h_in, const float* __restrict__ W_ih,
                            const float* __restrict__ b_ih, const float* __restrict__ b_hh,
                            int in_d) {
    extern __shared__ float sm[];
    float* sWT = sm;
    float* sh  = sm + 64 * 257;
    int tid = threadIdx.x;
    for (int i = tid; i < in_d * 256; i += 256) {
        int j = i / in_d, k = i - j * in_d;
        sWT[k * 257 + j] = W_ih[i];
    }
    int base = blockIdx.x * 8;
    for (int i = tid; i < 8 * in_d; i += 256) sh[i] = h_in[(size_t)base * in_d + i];
    float bias = b_ih[tid] + b_hh[tid];
    int dst = 4 * (tid & 63) + (tid >> 6);   // interleave: col = 4*unit + gate
    __syncthreads();
#pragma unroll
    for (int m = 0; m < 8; m++) {
        float acc = bias;
        for (int k = 0; k < in_d; k++) acc = fmaf(sh[m * in_d + k], sWT[k * 257 + tid], acc);
        g_Xg[(size_t)(base + m) * 256 + dst] = acc;
    }
}

// ---------------- HMMA LSTM recurrence ----------------
// CTA: 128 threads (4 warps), 64 nodes. Warp w owns gate-cols [w*64, w*64+64).
// Per step: gates[64,256] = h[64,64] @ W_hh^T, bf16x3 extended-K (hi*hi + hi*lo + lo*hi).
#define AST 72                                   // padded bf16 stride (conflict-free ldmatrix)
#define OFF_BH 0
#define OFF_BL (256 * AST * 2)                   // 36864
#define OFF_A  (2 * 256 * AST * 2)               // 73728
#define ABUF   (64 * AST * 2)                    // 9216 per (buf,src) tile
#define LSTM_SMEM (OFF_A + 4 * ABUF)             // 110592

__global__ __launch_bounds__(128, 2) void lstm_mma_kernel(const float* __restrict__ W_hh) {
    extern __shared__ char smem[];
    uint32_t sb = smem_u32(smem);
    int tid = threadIdx.x, lane = tid & 31, w = tid >> 5;
    int q = lane & 3, rh = lane >> 2;

    // W prep: gate-interleaved rows, bf16 hi/lo split
    for (int i = tid; i < 256 * 64; i += 128) {
        int j = i >> 6, k = i & 63;
        int col = 4 * (j & 63) + (j >> 6);
        float wv = W_hh[i];
        __nv_bfloat16 hh = __float2bfloat16_rn(wv);
        __nv_bfloat16 hl = __float2bfloat16_rn(wv - __bfloat162float(hh));
        ((__nv_bfloat16*)(smem + OFF_BH))[col * AST + k] = hh;
        ((__nv_bfloat16*)(smem + OFF_BL))[col * AST + k] = hl;
    }
    __syncthreads();

    int base = blockIdx.x * 64;
    float c[32];
#pragma unroll
    for (int i = 0; i < 32; i++) c[i] = 0.f;

    // ldmatrix lane offsets
    uint32_t aoff = (uint32_t)(((lane & 15) * AST + (lane >> 4) * 8) * 2);
    uint32_t boff = (uint32_t)(((w * 64 + (lane & 7)) * AST + ((lane >> 3) & 1) * 8) * 2);

    for (int t = 0; t < DD; t++) {
        if (t) __syncthreads();
        int rb = (t - 1) & 1;
        int wb = t & 1;

        int idxL[4], idxH[4];
#pragma unroll
        for (int mi = 0; mi < 4; mi++) {
            int rl = mi * 16 + rh;
            idxL[mi] = g_nbr_sorted[min(base + rl, NN - 1) * DD + t];
            idxH[mi] = g_nbr_sorted[min(base + rl + 8, NN - 1) * DD + t];
        }

#pragma unroll
        for (int nb = 0; nb < 2; nb++) {
            float d[4][4][4];
#pragma unroll
            for (int mi = 0; mi < 4; mi++)
#pragma unroll
                for (int nj = 0; nj < 4; nj++)
#pragma unroll
                    for (int e = 0; e < 4; e++) d[mi][nj][e] = 0.f;

            if (t) {
                uint32_t aBH = sb + OFF_A + (uint32_t)rb * (2 * ABUF) + aoff;
                uint32_t aBL = aBH + ABUF;
#pragma unroll
                for (int kc = 0; kc < 64; kc += 16) {
                    uint32_t ah[4][4], al[4][4], bh[4][2], bl[4][2];
#pragma unroll
                    for (int mi = 0; mi < 4; mi++)
                        ldsm4(ah[mi], aBH + (uint32_t)((mi * 16 * AST + kc) * 2));
#pragma unroll
                    for (int nj = 0; nj < 4; nj++)
                        ldsm2(bh[nj], sb + OFF_BH + boff + (uint32_t)((((nb * 4 + nj) * 8) * AST + kc) * 2));
#pragma unroll
                    for (int mi = 0; mi < 4; mi++)
#pragma unroll
                        for (int nj = 0; nj < 4; nj++) mma_bf16(d[mi][nj], ah[mi], bh[nj]);
#pragma unroll
                    for (int nj = 0; nj < 4; nj++)
                        ldsm2(bl[nj], sb + OFF_BL + boff + (uint32_t)((((nb * 4 + nj) * 8) * AST + kc) * 2));
#pragma unroll
                    for (int mi = 0; mi < 4; mi++)
#pragma unroll
                        for (int nj = 0; nj < 4; nj++) mma_bf16(d[mi][nj], ah[mi], bl[nj]);
#pragma unroll
                    for (int mi = 0; mi < 4; mi++)
                        ldsm4(al[mi], aBL + (uint32_t)((mi * 16 * AST + kc) * 2));
#pragma unroll
                    for (int mi = 0; mi < 4; mi++)
#pragma unroll
                        for (int nj = 0; nj < 4; nj++) mma_bf16(d[mi][nj], al[mi], bh[nj]);
                }
            }

            // epilogue
            __nv_bfloat16* sAh = (__nv_bfloat16*)(smem + OFF_A + (size_t)wb * (2 * ABUF));
            __nv_bfloat16* sAl = (__nv_bfloat16*)(smem + OFF_A + (size_t)wb * (2 * ABUF) + ABUF);
#pragma unroll
            for (int mi = 0; mi < 4; mi++) {
#pragma unroll
                for (int nj = 0; nj < 4; nj++) {
                    int col = w * 64 + (nb * 4 + nj) * 8 + 2 * q;
                    float2 xL = __ldg((const float2*)(g_Xg + (size_t)idxL[mi] * 256 + col));
                    float2 xH = __ldg((const float2*)(g_Xg + (size_t)idxH[mi] * 256 + col));
                    float d0 = d[mi][nj][0] + xL.x, d1 = d[mi][nj][1] + xL.y;
                    float d2 = d[mi][nj][2] + xH.x, d3 = d[mi][nj][3] + xH.y;
                    float sa = (q & 1) ? d0 : d2;
                    float sbv = (q & 1) ? d1 : d3;
                    float ra = __shfl_xor_sync(0xFFFFFFFFu, sa, 1);
                    float rv = __shfl_xor_sync(0xFFFFFFFFu, sbv, 1);
                    float I, F, G, O;
                    if (q & 1) { I = ra; F = rv; G = d2; O = d3; }
                    else       { I = d0; F = d1; G = ra; O = rv; }
                    int ci = mi * 8 + nb * 4 + nj;
                    float cc = fmaf(sigta(F), c[ci], sigta(I) * tanha(G));
                    c[ci] = cc;
                    float h = sigta(O) * tanha(cc);
                    int u = w * 16 + (nb * 4 + nj) * 2 + (q >> 1);
                    int row = mi * 16 + rh + ((q & 1) ? 8 : 0);
                    __nv_bfloat16 hh = __float2bfloat16_rn(h);
                    __nv_bfloat16 hl = __float2bfloat16_rn(h - __bfloat162float(hh));
                    sAh[row * AST + u] = hh;
                    sAl[row * AST + u] = hl;
                    if (t == DD - 1) {
                        int node = base + row;
                        if (node < NN) g_agg[(size_t)node * 64 + u] = h;
                    }
                }
            }
        }
    }
}

// ---------------- layer combine: h_out = relu([h_in, agg] @ Wl.T + bl) ----------------
__global__ void combine_kernel(const float* __restrict__ h_in, const float* __restrict__ Wl,
                               const float* __restrict__ bl, int in_d, float* __restrict__ h_out) {
    __shared__ float sWT[128 * 65];
    __shared__ float scomb[4][128];
    int K = in_d + 64;
    int tid = threadIdx.x;
    for (int i = tid; i < 64 * K; i += 256) {
        int j = i / K, k = i - j * K;
        sWT[k * 65 + j] = Wl[i];
    }
    int base = blockIdx.x * 4;
    for (int i = tid; i < 4 * in_d; i += 256) {
        int m = i / in_d;
        scomb[m][i - m * in_d] = h_in[(size_t)base * in_d + i];
    }
    for (int i = tid; i < 4 * 64; i += 256)
        scomb[i >> 6][in_d + (i & 63)] = g_agg[(size_t)base * 64 + i];
    __syncthreads();
    int m = tid >> 6, j = tid & 63;
    float acc = bl[j];
    for (int k = 0; k < K; k++) acc = fmaf(scomb[m][k], sWT[k * 65 + j], acc);
    h_out[(size_t)(base + m) * 64 + j] = fmaxf(acc, 0.f);
}

// ---------------- output head ----------------
__global__ void out_kernel(const float* __restrict__ h, const float* __restrict__ W_out,
                           const float* __restrict__ b_out, float* __restrict__ out) {
    int gw = (blockIdx.x * blockDim.x + threadIdx.x) >> 5;
    int lane = threadIdx.x & 31;
    if (gw >= NN) return;
    float2 hv = *(const float2*)(h + (size_t)gw * 64 + 2 * lane);
    float2 wv = *(const float2*)(W_out + 2 * lane);
    float s = hv.x * wv.x + hv.y * wv.y;
#pragma unroll
    for (int o = 16; o; o >>= 1) s += __shfl_xor_sync(0xFFFFFFFFu, s, o);
    if (lane == 0) out[gw] = s + b_out[0];
}

// ---------------- launch ----------------
extern "C" void kernel_launch(void* const* d_in, const int* in_sizes, int n_in,
                              void* d_out, int out_size) {
    (void)in_sizes; (void)n_in; (void)out_size;
    const float* nf   = (const float*)d_in[0];
    const int*   nbr  = (const int*)d_in[1];
    const float* Wout = (const float*)d_in[20];
    const float* bout = (const float*)d_in[21];
    float* out = (float*)d_out;

    float *hA = nullptr, *hB = nullptr;
    cudaGetSymbolAddress((void**)&hA, g_hA);
    cudaGetSymbolAddress((void**)&hB, g_hB);

    cudaFuncSetAttribute(lstm_mma_kernel, cudaFuncAttributeMaxDynamicSharedMemorySize, LSTM_SMEM);
    cudaFuncSetAttribute(proj_kernel, cudaFuncAttributeMaxDynamicSharedMemorySize, PROJ_SMEM);

    sort_kernel<<<NN / 8, 256>>>(nbr);

    const float* h_in = nf;
    float* houts[3] = { hA, hB, hA };
    int lstm_grid = (NN + 63) / 64;   // 313
    for (int l = 0; l < 3; l++) {
        const float* W_ih = (const float*)d_in[2 + 6 * l + 0];
        const float* W_hh = (const float*)d_in[2 + 6 * l + 1];
        const float* b_ih = (const float*)d_in[2 + 6 * l + 2];
        const float* b_hh = (const float*)d_in[2 + 6 * l + 3];
        const float* Wl   = (const float*)d_in[2 + 6 * l + 4];
        const float* bl   = (const float*)d_in[2 + 6 * l + 5];
        int in_d = (l == 0) ? 3 : 64;

        proj_kernel<<<NN / 8, 256, PROJ_SMEM>>>(h_in, W_ih, b_ih, b_hh, in_d);
        lstm_mma_kernel<<<lstm_grid, 128, LSTM_SMEM>>>(W_hh);
        combine_kernel<<<NN / 4, 256>>>(h_in, Wl, bl, in_d, houts[l]);
        h_in = houts[l];
    }
    out_kernel<<<NN / 8, 256>>>(h_in, Wout, bout, out);
}

// round 5
// speedup vs baseline: 2.4043x; 1.3806x over previous
#include <cuda_runtime.h>
#include <cuda_fp16.h>
#include <cstdint>

#define NN 20000
#define DD 32
#define HH 64

typedef unsigned long long ull;

// ---------------- scratch (static device globals; no allocation) ----------------
__device__ int   g_nbr_sorted[NN * DD];
__device__ float g_Xg[(size_t)NN * 256];     // gate-interleaved: col = 4*u + gate
__device__ float g_hA[(size_t)NN * HH];
__device__ float g_hB[(size_t)NN * HH];
__device__ float g_agg[(size_t)NN * HH];

// ---------------- helpers ----------------
__device__ __forceinline__ uint32_t smem_u32(const void* p) {
    uint32_t a;
    asm("{ .reg .u64 t; cvta.to.shared.u64 t, %1; cvt.u32.u64 %0, t; }" : "=r"(a) : "l"(p));
    return a;
}
__device__ __forceinline__ float tanha(float x) {
    float r; asm("tanh.approx.f32 %0, %1;" : "=f"(r) : "f"(x)); return r;
}
__device__ __forceinline__ float sigta(float x) { return fmaf(tanha(0.5f * x), 0.5f, 0.5f); }

__device__ __forceinline__ void ldsm4(uint32_t* r, uint32_t a) {
    asm volatile("ldmatrix.sync.aligned.m8n8.x4.shared.b16 {%0,%1,%2,%3}, [%4];"
        : "=r"(r[0]), "=r"(r[1]), "=r"(r[2]), "=r"(r[3]) : "r"(a));
}
__device__ __forceinline__ void ldsm2(uint32_t* r, uint32_t a) {
    asm volatile("ldmatrix.sync.aligned.m8n8.x2.shared.b16 {%0,%1}, [%2];"
        : "=r"(r[0]), "=r"(r[1]) : "r"(a));
}
__device__ __forceinline__ void mma_f16(float* d, const uint32_t* a, const uint32_t* b) {
    asm volatile("mma.sync.aligned.m16n8k16.row.col.f32.f16.f16.f32 "
        "{%0,%1,%2,%3}, {%4,%5,%6,%7}, {%8,%9}, {%0,%1,%2,%3};"
        : "+f"(d[0]), "+f"(d[1]), "+f"(d[2]), "+f"(d[3])
        : "r"(a[0]), "r"(a[1]), "r"(a[2]), "r"(a[3]), "r"(b[0]), "r"(b[1]));
}

// ---------------- neighbor sort ----------------
__global__ void sort_kernel(const int* __restrict__ nbr) {
    int gw = (blockIdx.x * blockDim.x + threadIdx.x) >> 5;
    int lane = threadIdx.x & 31;
    if (gw >= NN) return;
    int v = nbr[gw * DD + lane];
#pragma unroll
    for (int k = 2; k <= 32; k <<= 1) {
#pragma unroll
        for (int j = k >> 1; j > 0; j >>= 1) {
            int p = __shfl_xor_sync(0xFFFFFFFFu, v, j);
            bool up = ((lane & k) == 0);
            bool lo = ((lane & j) == 0);
            int mn = min(v, p), mx = max(v, p);
            v = (up == lo) ? mn : mx;
        }
    }
    g_nbr_sorted[gw * DD + lane] = v;
}

// ---------------- Xg = h_in @ W_ih.T + (b_ih + b_hh), gate-interleaved cols ----------------
#define PROJ_SMEM (64 * 257 * 4 + 8 * 64 * 4)
__global__ void proj_kernel(const float* __restrict__ h_in, const float* __restrict__ W_ih,
                            const float* __restrict__ b_ih, const float* __restrict__ b_hh,
                            int in_d) {
    extern __shared__ float sm[];
    float* sWT = sm;
    float* sh  = sm + 64 * 257;
    int tid = threadIdx.x;
    for (int i = tid; i < in_d * 256; i += 256) {
        int j = i / in_d, k = i - j * in_d;
        sWT[k * 257 + j] = W_ih[i];
    }
    int base = blockIdx.x * 8;
    for (int i = tid; i < 8 * in_d; i += 256) sh[i] = h_in[(size_t)base * in_d + i];
    float bias = b_ih[tid] + b_hh[tid];
    int dst = 4 * (tid & 63) + (tid >> 6);   // interleave: col = 4*unit + gate
    __syncthreads();
#pragma unroll
    for (int m = 0; m < 8; m++) {
        float acc = bias;
        for (int k = 0; k < in_d; k++) acc = fmaf(sh[m * in_d + k], sWT[k * 257 + tid], acc);
        g_Xg[(size_t)(base + m) * 256 + dst] = acc;
    }
}

// ---------------- HMMA LSTM recurrence (fp16x2 split, one wave) ----------------
// Grid 304 (=152*2, uniform 2 CTAs/SM). CTA: 128 threads, 66 nodes (padded to 80 rows).
// Per step: gates[80,256] = h[80,64] @ W_hh^T via fp16x2: ah*bh + ah*bl.
#define M_TILES 5
#define NPC 66
#define A_ROWS 80
#define AST 72                                   // padded fp16 stride
#define OFF_BH 0
#define OFF_BL (256 * AST * 2)                   // 36864
#define OFF_A  (2 * 256 * AST * 2)               // 73728
#define ABUF   (A_ROWS * AST * 2)                // 11520
#define LSTM_SMEM (OFF_A + 2 * ABUF)             // 96768

__global__ __launch_bounds__(128, 2) void lstm_mma_kernel(const float* __restrict__ W_hh) {
    extern __shared__ char smem[];
    uint32_t sb = smem_u32(smem);
    int tid = threadIdx.x, lane = tid & 31, w = tid >> 5;
    int q = lane & 3, rh = lane >> 2;

    // W prep: gate-interleaved rows, fp16 hi/lo split (lo = exact residual, fits fp16)
    for (int i = tid; i < 256 * 64; i += 128) {
        int j = i >> 6, k = i & 63;
        int col = 4 * (j & 63) + (j >> 6);
        float wv = W_hh[i];
        __half hh = __float2half_rn(wv);
        __half hl = __float2half_rn(wv - __half2float(hh));
        ((__half*)(smem + OFF_BH))[col * AST + k] = hh;
        ((__half*)(smem + OFF_BL))[col * AST + k] = hl;
    }
    __syncthreads();

    int base = blockIdx.x * NPC;
    float c[M_TILES * 8];
#pragma unroll
    for (int i = 0; i < M_TILES * 8; i++) c[i] = 0.f;

    uint32_t aoff = (uint32_t)(((lane & 15) * AST + (lane >> 4) * 8) * 2);
    uint32_t boff = (uint32_t)(((w * 64 + (lane & 7)) * AST + ((lane >> 3) & 1) * 8) * 2);

    for (int t = 0; t < DD; t++) {
        if (t) __syncthreads();
        int rb = (t - 1) & 1;
        int wb = t & 1;

        int idxL[M_TILES], idxH[M_TILES];
#pragma unroll
        for (int mi = 0; mi < M_TILES; mi++) {
            int rl = mi * 16 + rh;
            idxL[mi] = g_nbr_sorted[min(base + rl, NN - 1) * DD + t];
            idxH[mi] = g_nbr_sorted[min(base + rl + 8, NN - 1) * DD + t];
        }

#pragma unroll
        for (int nb = 0; nb < 2; nb++) {
            float d[M_TILES][4][4];
#pragma unroll
            for (int mi = 0; mi < M_TILES; mi++)
#pragma unroll
                for (int nj = 0; nj < 4; nj++)
#pragma unroll
                    for (int e = 0; e < 4; e++) d[mi][nj][e] = 0.f;

            if (t) {
                uint32_t aB = sb + OFF_A + (uint32_t)rb * ABUF + aoff;
#pragma unroll
                for (int kc = 0; kc < 64; kc += 16) {
                    uint32_t ah[M_TILES][4];
#pragma unroll
                    for (int mi = 0; mi < M_TILES; mi++)
                        ldsm4(ah[mi], aB + (uint32_t)((mi * 16 * AST + kc) * 2));
#pragma unroll
                    for (int nj = 0; nj < 4; nj++) {
                        uint32_t bcol = (uint32_t)((((nb * 4 + nj) * 8) * AST + kc) * 2);
                        uint32_t bh[2], bl[2];
                        ldsm2(bh, sb + OFF_BH + boff + bcol);
                        ldsm2(bl, sb + OFF_BL + boff + bcol);
#pragma unroll
                        for (int mi = 0; mi < M_TILES; mi++) mma_f16(d[mi][nj], ah[mi], bh);
#pragma unroll
                        for (int mi = 0; mi < M_TILES; mi++) mma_f16(d[mi][nj], ah[mi], bl);
                    }
                }
            }

            // epilogue
            __half* sA = (__half*)(smem + OFF_A + (size_t)wb * ABUF);
#pragma unroll
            for (int mi = 0; mi < M_TILES; mi++) {
                // batch the Xg gathers for this mi (hide L2 latency)
                float2 xL[4], xH[4];
#pragma unroll
                for (int nj = 0; nj < 4; nj++) {
                    int col = w * 64 + (nb * 4 + nj) * 8 + 2 * q;
                    xL[nj] = __ldg((const float2*)(g_Xg + (size_t)idxL[mi] * 256 + col));
                    xH[nj] = __ldg((const float2*)(g_Xg + (size_t)idxH[mi] * 256 + col));
                }
#pragma unroll
                for (int nj = 0; nj < 4; nj++) {
                    float d0 = d[mi][nj][0] + xL[nj].x, d1 = d[mi][nj][1] + xL[nj].y;
                    float d2 = d[mi][nj][2] + xH[nj].x, d3 = d[mi][nj][3] + xH[nj].y;
                    float sa = (q & 1) ? d0 : d2;
                    float sbv = (q & 1) ? d1 : d3;
                    float ra = __shfl_xor_sync(0xFFFFFFFFu, sa, 1);
                    float rv = __shfl_xor_sync(0xFFFFFFFFu, sbv, 1);
                    float I, F, G, O;
                    if (q & 1) { I = ra; F = rv; G = d2; O = d3; }
                    else       { I = d0; F = d1; G = ra; O = rv; }
                    int ci = mi * 8 + nb * 4 + nj;
                    float cc = fmaf(sigta(F), c[ci], sigta(I) * tanha(G));
                    c[ci] = cc;
                    float h = sigta(O) * tanha(cc);
                    int u = w * 16 + (nb * 4 + nj) * 2 + (q >> 1);
                    int row = mi * 16 + rh + ((q & 1) ? 8 : 0);
                    sA[row * AST + u] = __float2half_rn(h);
                    if (t == DD - 1) {
                        int node = base + row;
                        if (row < NPC && node < NN) g_agg[(size_t)node * 64 + u] = h;
                    }
                }
            }
        }
    }
}

// ---------------- layer combine: h_out = relu([h_in, agg] @ Wl.T + bl) ----------------
__global__ void combine_kernel(const float* __restrict__ h_in, const float* __restrict__ Wl,
                               const float* __restrict__ bl, int in_d, float* __restrict__ h_out) {
    __shared__ float sWT[128 * 65];
    __shared__ float scomb[4][128];
    int K = in_d + 64;
    int tid = threadIdx.x;
    for (int i = tid; i < 64 * K; i += 256) {
        int j = i / K, k = i - j * K;
        sWT[k * 65 + j] = Wl[i];
    }
    int base = blockIdx.x * 4;
    for (int i = tid; i < 4 * in_d; i += 256) {
        int m = i / in_d;
        scomb[m][i - m * in_d] = h_in[(size_t)base * in_d + i];
    }
    for (int i = tid; i < 4 * 64; i += 256)
        scomb[i >> 6][in_d + (i & 63)] = g_agg[(size_t)base * 64 + i];
    __syncthreads();
    int m = tid >> 6, j = tid & 63;
    float acc = bl[j];
    for (int k = 0; k < K; k++) acc = fmaf(scomb[m][k], sWT[k * 65 + j], acc);
    h_out[(size_t)(base + m) * 64 + j] = fmaxf(acc, 0.f);
}

// ---------------- output head ----------------
__global__ void out_kernel(const float* __restrict__ h, const float* __restrict__ W_out,
                           const float* __restrict__ b_out, float* __restrict__ out) {
    int gw = (blockIdx.x * blockDim.x + threadIdx.x) >> 5;
    int lane = threadIdx.x & 31;
    if (gw >= NN) return;
    float2 hv = *(const float2*)(h + (size_t)gw * 64 + 2 * lane);
    float2 wv = *(const float2*)(W_out + 2 * lane);
    float s = hv.x * wv.x + hv.y * wv.y;
#pragma unroll
    for (int o = 16; o; o >>= 1) s += __shfl_xor_sync(0xFFFFFFFFu, s, o);
    if (lane == 0) out[gw] = s + b_out[0];
}

// ---------------- launch ----------------
extern "C" void kernel_launch(void* const* d_in, const int* in_sizes, int n_in,
                              void* d_out, int out_size) {
    (void)in_sizes; (void)n_in; (void)out_size;
    const float* nf   = (const float*)d_in[0];
    const int*   nbr  = (const int*)d_in[1];
    const float* Wout = (const float*)d_in[20];
    const float* bout = (const float*)d_in[21];
    float* out = (float*)d_out;

    float *hA = nullptr, *hB = nullptr;
    cudaGetSymbolAddress((void**)&hA, g_hA);
    cudaGetSymbolAddress((void**)&hB, g_hB);

    cudaFuncSetAttribute(lstm_mma_kernel, cudaFuncAttributeMaxDynamicSharedMemorySize, LSTM_SMEM);
    cudaFuncSetAttribute(proj_kernel, cudaFuncAttributeMaxDynamicSharedMemorySize, PROJ_SMEM);

    sort_kernel<<<NN / 8, 256>>>(nbr);

    const float* h_in = nf;
    float* houts[3] = { hA, hB, hA };
    int lstm_grid = (NN + NPC - 1) / NPC;   // 304 = 152 * 2, one uniform wave
    for (int l = 0; l < 3; l++) {
        const float* W_ih = (const float*)d_in[2 + 6 * l + 0];
        const float* W_hh = (const float*)d_in[2 + 6 * l + 1];
        const float* b_ih = (const float*)d_in[2 + 6 * l + 2];
        const float* b_hh = (const float*)d_in[2 + 6 * l + 3];
        const float* Wl   = (const float*)d_in[2 + 6 * l + 4];
        const float* bl   = (const float*)d_in[2 + 6 * l + 5];
        int in_d = (l == 0) ? 3 : 64;

        proj_kernel<<<NN / 8, 256, PROJ_SMEM>>>(h_in, W_ih, b_ih, b_hh, in_d);
        lstm_mma_kernel<<<lstm_grid, 128, LSTM_SMEM>>>(W_hh);
        combine_kernel<<<NN / 4, 256>>>(h_in, Wl, bl, in_d, houts[l]);
        h_in = houts[l];
    }
    out_kernel<<<NN / 8, 256>>>(h_in, Wout, bout, out);
}

// round 6
// speedup vs baseline: 3.4139x; 1.4199x over previous
#include <cuda_runtime.h>
#include <cuda_fp16.h>
#include <cstdint>

#define NN 20000
#define DD 32
#define HH 64

typedef unsigned long long ull;

// ---------------- scratch (static device globals; no allocation) ----------------
__device__ int   g_nbr_sorted[NN * DD];
__device__ float g_Xg[(size_t)NN * 256];     // gate-interleaved: col = 4*u + gate
__device__ float g_hA[(size_t)NN * HH];
__device__ float g_hB[(size_t)NN * HH];
__device__ float g_agg[(size_t)NN * HH];

// ---------------- helpers ----------------
__device__ __forceinline__ uint32_t smem_u32(const void* p) {
    uint32_t a;
    asm("{ .reg .u64 t; cvta.to.shared.u64 t, %1; cvt.u32.u64 %0, t; }" : "=r"(a) : "l"(p));
    return a;
}
__device__ __forceinline__ float tanha(float x) {
    float r; asm("tanh.approx.f32 %0, %1;" : "=f"(r) : "f"(x)); return r;
}
__device__ __forceinline__ float sigta(float x) { return fmaf(tanha(0.5f * x), 0.5f, 0.5f); }

__device__ __forceinline__ void ldsm4(uint32_t* r, uint32_t a) {
    asm volatile("ldmatrix.sync.aligned.m8n8.x4.shared.b16 {%0,%1,%2,%3}, [%4];"
        : "=r"(r[0]), "=r"(r[1]), "=r"(r[2]), "=r"(r[3]) : "r"(a));
}
__device__ __forceinline__ void ldsm2(uint32_t* r, uint32_t a) {
    asm volatile("ldmatrix.sync.aligned.m8n8.x2.shared.b16 {%0,%1}, [%2];"
        : "=r"(r[0]), "=r"(r[1]) : "r"(a));
}
__device__ __forceinline__ void mma_f16(float* d, const uint32_t* a, const uint32_t* b) {
    asm volatile("mma.sync.aligned.m16n8k16.row.col.f32.f16.f16.f32 "
        "{%0,%1,%2,%3}, {%4,%5,%6,%7}, {%8,%9}, {%0,%1,%2,%3};"
        : "+f"(d[0]), "+f"(d[1]), "+f"(d[2]), "+f"(d[3])
        : "r"(a[0]), "r"(a[1]), "r"(a[2]), "r"(a[3]), "r"(b[0]), "r"(b[1]));
}

// ---------------- neighbor sort ----------------
__global__ void sort_kernel(const int* __restrict__ nbr) {
    int gw = (blockIdx.x * blockDim.x + threadIdx.x) >> 5;
    int lane = threadIdx.x & 31;
    if (gw >= NN) return;
    int v = nbr[gw * DD + lane];
#pragma unroll
    for (int k = 2; k <= 32; k <<= 1) {
#pragma unroll
        for (int j = k >> 1; j > 0; j >>= 1) {
            int p = __shfl_xor_sync(0xFFFFFFFFu, v, j);
            bool up = ((lane & k) == 0);
            bool lo = ((lane & j) == 0);
            int mn = min(v, p), mx = max(v, p);
            v = (up == lo) ? mn : mx;
        }
    }
    g_nbr_sorted[gw * DD + lane] = v;
}

// ---------------- Xg = h_in @ W_ih.T + (b_ih + b_hh), gate-interleaved cols ----------------
#define PROJ_SMEM (64 * 257 * 4 + 8 * 64 * 4)
template <int IN_D>
__global__ void proj_kernel(const float* __restrict__ h_in, const float* __restrict__ W_ih,
                            const float* __restrict__ b_ih, const float* __restrict__ b_hh) {
    extern __shared__ float sm[];
    float* sWT = sm;
    float* sh  = sm + 64 * 257;
    int tid = threadIdx.x;
    for (int i = tid; i < IN_D * 256; i += 256) {
        int j = i / IN_D, k = i - j * IN_D;
        sWT[k * 257 + j] = W_ih[i];
    }
    int base = blockIdx.x * 8;
    for (int i = tid; i < 8 * IN_D; i += 256) sh[i] = h_in[(size_t)base * IN_D + i];
    float bias = b_ih[tid] + b_hh[tid];
    int dst = 4 * (tid & 63) + (tid >> 6);   // interleave: col = 4*unit + gate
    __syncthreads();
#pragma unroll
    for (int m = 0; m < 8; m++) {
        float acc = bias;
#pragma unroll
        for (int k = 0; k < IN_D; k++) acc = fmaf(sh[m * IN_D + k], sWT[k * 257 + tid], acc);
        g_Xg[(size_t)(base + m) * 256 + dst] = acc;
    }
}

// ---------------- HMMA LSTM recurrence (single fp16 pass, 3 CTAs/SM, one wave) ----------------
// Grid 455 (<=456=152*3). CTA: 128 threads, 44 nodes (padded to 48 rows = 3 m16 tiles).
// Per step: gates[48,256] = h[48,64] @ W_hh^T, fp16 inputs, fp32 accum.
#define M_TILES 3
#define NPC 44
#define A_ROWS 48
#define AST 72                                   // padded fp16 stride
#define OFF_B 0
#define OFF_A (256 * AST * 2)                    // 36864
#define ABUF  (A_ROWS * AST * 2)                 // 6912
#define LSTM_SMEM (OFF_A + 2 * ABUF)             // 50688

__global__ __launch_bounds__(128, 3) void lstm_mma_kernel(const float* __restrict__ W_hh) {
    extern __shared__ char smem[];
    uint32_t sb = smem_u32(smem);
    int tid = threadIdx.x, lane = tid & 31, w = tid >> 5;
    int q = lane & 3, rh = lane >> 2;

    // W prep: gate-interleaved rows, fp16
    for (int i = tid; i < 256 * 64; i += 128) {
        int j = i >> 6, k = i & 63;
        int col = 4 * (j & 63) + (j >> 6);
        ((__half*)(smem + OFF_B))[col * AST + k] = __float2half_rn(W_hh[i]);
    }
    __syncthreads();

    int base = blockIdx.x * NPC;
    float c[M_TILES * 8];
#pragma unroll
    for (int i = 0; i < M_TILES * 8; i++) c[i] = 0.f;

    uint32_t aoff = (uint32_t)(((lane & 15) * AST + (lane >> 4) * 8) * 2);
    uint32_t boff = (uint32_t)(((w * 64 + (lane & 7)) * AST + ((lane >> 3) & 1) * 8) * 2);

    for (int t = 0; t < DD; t++) {
        if (t) __syncthreads();
        int rb = (t - 1) & 1;
        int wb = t & 1;

        int idxL[M_TILES], idxH[M_TILES];
#pragma unroll
        for (int mi = 0; mi < M_TILES; mi++) {
            int rl = mi * 16 + rh;
            idxL[mi] = g_nbr_sorted[min(base + rl, NN - 1) * DD + t];
            idxH[mi] = g_nbr_sorted[min(base + rl + 8, NN - 1) * DD + t];
        }

#pragma unroll
        for (int nb = 0; nb < 2; nb++) {
            float d[M_TILES][4][4];
#pragma unroll
            for (int mi = 0; mi < M_TILES; mi++)
#pragma unroll
                for (int nj = 0; nj < 4; nj++)
#pragma unroll
                    for (int e = 0; e < 4; e++) d[mi][nj][e] = 0.f;

            if (t) {
                uint32_t aB = sb + OFF_A + (uint32_t)rb * ABUF + aoff;
#pragma unroll
                for (int kc = 0; kc < 64; kc += 16) {
                    uint32_t ah[M_TILES][4];
#pragma unroll
                    for (int mi = 0; mi < M_TILES; mi++)
                        ldsm4(ah[mi], aB + (uint32_t)((mi * 16 * AST + kc) * 2));
#pragma unroll
                    for (int nj = 0; nj < 4; nj++) {
                        uint32_t bh[2];
                        ldsm2(bh, sb + OFF_B + boff + (uint32_t)((((nb * 4 + nj) * 8) * AST + kc) * 2));
#pragma unroll
                        for (int mi = 0; mi < M_TILES; mi++) mma_f16(d[mi][nj], ah[mi], bh);
                    }
                }
            }

            // epilogue
            __half* sA = (__half*)(smem + OFF_A + (size_t)wb * ABUF);
#pragma unroll
            for (int mi = 0; mi < M_TILES; mi++) {
                float2 xL[4], xH[4];
#pragma unroll
                for (int nj = 0; nj < 4; nj++) {
                    int col = w * 64 + (nb * 4 + nj) * 8 + 2 * q;
                    xL[nj] = __ldg((const float2*)(g_Xg + (size_t)idxL[mi] * 256 + col));
                    xH[nj] = __ldg((const float2*)(g_Xg + (size_t)idxH[mi] * 256 + col));
                }
#pragma unroll
                for (int nj = 0; nj < 4; nj++) {
                    float d0 = d[mi][nj][0] + xL[nj].x, d1 = d[mi][nj][1] + xL[nj].y;
                    float d2 = d[mi][nj][2] + xH[nj].x, d3 = d[mi][nj][3] + xH[nj].y;
                    float sa = (q & 1) ? d0 : d2;
                    float sbv = (q & 1) ? d1 : d3;
                    float ra = __shfl_xor_sync(0xFFFFFFFFu, sa, 1);
                    float rv = __shfl_xor_sync(0xFFFFFFFFu, sbv, 1);
                    float I, F, G, O;
                    if (q & 1) { I = ra; F = rv; G = d2; O = d3; }
                    else       { I = d0; F = d1; G = ra; O = rv; }
                    int ci = mi * 8 + nb * 4 + nj;
                    float cc = fmaf(sigta(F), c[ci], sigta(I) * tanha(G));
                    c[ci] = cc;
                    float h = sigta(O) * tanha(cc);
                    int u = w * 16 + (nb * 4 + nj) * 2 + (q >> 1);
                    int row = mi * 16 + rh + ((q & 1) ? 8 : 0);
                    sA[row * AST + u] = __float2half_rn(h);
                    if (t == DD - 1) {
                        int node = base + row;
                        if (row < NPC && node < NN) g_agg[(size_t)node * 64 + u] = h;
                    }
                }
            }
        }
    }
}

// ---------------- layer combine: h_out = relu([h_in, agg] @ Wl.T + bl) ----------------
template <int IN_D>
__global__ void combine_kernel(const float* __restrict__ h_in, const float* __restrict__ Wl,
                               const float* __restrict__ bl, float* __restrict__ h_out) {
    constexpr int K = IN_D + 64;
    __shared__ float sWT[128 * 65];
    __shared__ float scomb[4][128];
    int tid = threadIdx.x;
    for (int i = tid; i < 64 * K; i += 256) {
        int j = i / K, k = i - j * K;
        sWT[k * 65 + j] = Wl[i];
    }
    int base = blockIdx.x * 4;
    for (int i = tid; i < 4 * IN_D; i += 256) {
        int m = i / IN_D;
        scomb[m][i - m * IN_D] = h_in[(size_t)base * IN_D + i];
    }
    for (int i = tid; i < 4 * 64; i += 256)
        scomb[i >> 6][IN_D + (i & 63)] = g_agg[(size_t)base * 64 + i];
    __syncthreads();
    int m = tid >> 6, j = tid & 63;
    float acc = bl[j];
#pragma unroll
    for (int k = 0; k < K; k++) acc = fmaf(scomb[m][k], sWT[k * 65 + j], acc);
    h_out[(size_t)(base + m) * 64 + j] = fmaxf(acc, 0.f);
}

// ---------------- output head ----------------
__global__ void out_kernel(const float* __restrict__ h, const float* __restrict__ W_out,
                           const float* __restrict__ b_out, float* __restrict__ out) {
    int gw = (blockIdx.x * blockDim.x + threadIdx.x) >> 5;
    int lane = threadIdx.x & 31;
    if (gw >= NN) return;
    float2 hv = *(const float2*)(h + (size_t)gw * 64 + 2 * lane);
    float2 wv = *(const float2*)(W_out + 2 * lane);
    float s = hv.x * wv.x + hv.y * wv.y;
#pragma unroll
    for (int o = 16; o; o >>= 1) s += __shfl_xor_sync(0xFFFFFFFFu, s, o);
    if (lane == 0) out[gw] = s + b_out[0];
}

// ---------------- launch ----------------
extern "C" void kernel_launch(void* const* d_in, const int* in_sizes, int n_in,
                              void* d_out, int out_size) {
    (void)in_sizes; (void)n_in; (void)out_size;
    const float* nf   = (const float*)d_in[0];
    const int*   nbr  = (const int*)d_in[1];
    const float* Wout = (const float*)d_in[20];
    const float* bout = (const float*)d_in[21];
    float* out = (float*)d_out;

    float *hA = nullptr, *hB = nullptr;
    cudaGetSymbolAddress((void**)&hA, g_hA);
    cudaGetSymbolAddress((void**)&hB, g_hB);

    cudaFuncSetAttribute(lstm_mma_kernel, cudaFuncAttributeMaxDynamicSharedMemorySize, LSTM_SMEM);
    cudaFuncSetAttribute(proj_kernel<3>,  cudaFuncAttributeMaxDynamicSharedMemorySize, PROJ_SMEM);
    cudaFuncSetAttribute(proj_kernel<64>, cudaFuncAttributeMaxDynamicSharedMemorySize, PROJ_SMEM);

    sort_kernel<<<NN / 8, 256>>>(nbr);

    const float* h_in = nf;
    float* houts[3] = { hA, hB, hA };
    int lstm_grid = (NN + NPC - 1) / NPC;   // 455 <= 456 = 152*3, one wave at 3 CTAs/SM
    for (int l = 0; l < 3; l++) {
        const float* W_ih = (const float*)d_in[2 + 6 * l + 0];
        const float* W_hh = (const float*)d_in[2 + 6 * l + 1];
        const float* b_ih = (const float*)d_in[2 + 6 * l + 2];
        const float* b_hh = (const float*)d_in[2 + 6 * l + 3];
        const float* Wl   = (const float*)d_in[2 + 6 * l + 4];
        const float* bl   = (const float*)d_in[2 + 6 * l + 5];

        if (l == 0) proj_kernel<3><<<NN / 8, 256, PROJ_SMEM>>>(h_in, W_ih, b_ih, b_hh);
        else        proj_kernel<64><<<NN / 8, 256, PROJ_SMEM>>>(h_in, W_ih, b_ih, b_hh);
        lstm_mma_kernel<<<lstm_grid, 128, LSTM_SMEM>>>(W_hh);
        if (l == 0) combine_kernel<3><<<NN / 4, 256>>>(h_in, Wl, bl, houts[l]);
        else        combine_kernel<64><<<NN / 4, 256>>>(h_in, Wl, bl, houts[l]);
        h_in = houts[l];
    }
    out_kernel<<<NN / 8, 256>>>(h_in, Wout, bout, out);
}

// round 7
// speedup vs baseline: 3.5083x; 1.0277x over previous
#include <cuda_runtime.h>
#include <cuda_fp16.h>
#include <cstdint>

#define NN 20000
#define DD 32
#define HH 64

typedef unsigned long long ull;

// ---------------- scratch (static device globals; no allocation) ----------------
__device__ int   g_nbr_sorted[NN * DD];
__device__ float g_Xg[(size_t)NN * 256];     // gate-interleaved: col = 4*u + gate
__device__ float g_hA[(size_t)NN * HH];
__device__ float g_hB[(size_t)NN * HH];
__device__ float g_agg[(size_t)NN * HH];

// ---------------- helpers ----------------
__device__ __forceinline__ uint32_t smem_u32(const void* p) {
    uint32_t a;
    asm("{ .reg .u64 t; cvta.to.shared.u64 t, %1; cvt.u32.u64 %0, t; }" : "=r"(a) : "l"(p));
    return a;
}
__device__ __forceinline__ float tanha(float x) {
    float r; asm("tanh.approx.f32 %0, %1;" : "=f"(r) : "f"(x)); return r;
}
// packed tanh of two floats via f16x2 MUFU (1 MUFU op for 2 values)
__device__ __forceinline__ float2 tanh2(float a, float b) {
    __half2 hv = __floats2half2_rn(a, b);
    uint32_t u = *(uint32_t*)&hv;
    uint32_t r;
    asm("tanh.approx.f16x2 %0, %1;" : "=r"(r) : "r"(u));
    __half2 hr = *(__half2*)&r;
    return __half22float2(hr);
}

__device__ __forceinline__ void ldsm4(uint32_t* r, uint32_t a) {
    asm volatile("ldmatrix.sync.aligned.m8n8.x4.shared.b16 {%0,%1,%2,%3}, [%4];"
        : "=r"(r[0]), "=r"(r[1]), "=r"(r[2]), "=r"(r[3]) : "r"(a));
}
__device__ __forceinline__ void ldsm2(uint32_t* r, uint32_t a) {
    asm volatile("ldmatrix.sync.aligned.m8n8.x2.shared.b16 {%0,%1}, [%2];"
        : "=r"(r[0]), "=r"(r[1]) : "r"(a));
}
__device__ __forceinline__ void mma_f16(float* d, const uint32_t* a, const uint32_t* b) {
    asm volatile("mma.sync.aligned.m16n8k16.row.col.f32.f16.f16.f32 "
        "{%0,%1,%2,%3}, {%4,%5,%6,%7}, {%8,%9}, {%0,%1,%2,%3};"
        : "+f"(d[0]), "+f"(d[1]), "+f"(d[2]), "+f"(d[3])
        : "r"(a[0]), "r"(a[1]), "r"(a[2]), "r"(a[3]), "r"(b[0]), "r"(b[1]));
}

// ---------------- neighbor sort ----------------
__global__ void sort_kernel(const int* __restrict__ nbr) {
    int gw = (blockIdx.x * blockDim.x + threadIdx.x) >> 5;
    int lane = threadIdx.x & 31;
    if (gw >= NN) return;
    int v = nbr[gw * DD + lane];
#pragma unroll
    for (int k = 2; k <= 32; k <<= 1) {
#pragma unroll
        for (int j = k >> 1; j > 0; j >>= 1) {
            int p = __shfl_xor_sync(0xFFFFFFFFu, v, j);
            bool up = ((lane & k) == 0);
            bool lo = ((lane & j) == 0);
            int mn = min(v, p), mx = max(v, p);
            v = (up == lo) ? mn : mx;
        }
    }
    g_nbr_sorted[gw * DD + lane] = v;
}

// ---------------- Xg = h_in @ W_ih.T + (b_ih + b_hh), gate-interleaved, 32 nodes/blk ----------------
#define PROJ_SMEM (64 * 257 * 4 + 32 * 64 * 4)
template <int IN_D>
__global__ void proj_kernel(const float* __restrict__ h_in, const float* __restrict__ W_ih,
                            const float* __restrict__ b_ih, const float* __restrict__ b_hh) {
    extern __shared__ float sm[];
    float* sWT = sm;
    float* sh  = sm + 64 * 257;
    int tid = threadIdx.x;
    for (int i = tid; i < IN_D * 256; i += 256) {
        int j = i / IN_D, k = i - j * IN_D;
        sWT[k * 257 + j] = W_ih[i];
    }
    int base = blockIdx.x * 32;
    for (int i = tid; i < 32 * IN_D; i += 256) sh[i] = h_in[(size_t)base * IN_D + i];
    float bias = b_ih[tid] + b_hh[tid];
    int dst = 4 * (tid & 63) + (tid >> 6);   // interleave: col = 4*unit + gate
    __syncthreads();
#pragma unroll 4
    for (int m = 0; m < 32; m++) {
        float acc = bias;
#pragma unroll
        for (int k = 0; k < IN_D; k++) acc = fmaf(sh[m * IN_D + k], sWT[k * 257 + tid], acc);
        g_Xg[(size_t)(base + m) * 256 + dst] = acc;
    }
}

// ---------------- HMMA LSTM recurrence (single fp16 pass, 3 CTAs/SM, one wave) ----------------
#define M_TILES 3
#define NPC 44
#define A_ROWS 48
#define AST 72
#define OFF_B 0
#define OFF_A (256 * AST * 2)                    // 36864
#define ABUF  (A_ROWS * AST * 2)                 // 6912
#define LSTM_SMEM (OFF_A + 2 * ABUF)             // 50688

__global__ __launch_bounds__(128, 3) void lstm_mma_kernel(const float* __restrict__ W_hh) {
    extern __shared__ char smem[];
    uint32_t sb = smem_u32(smem);
    int tid = threadIdx.x, lane = tid & 31, w = tid >> 5;
    int q = lane & 3, rh = lane >> 2;

    for (int i = tid; i < 256 * 64; i += 128) {
        int j = i >> 6, k = i & 63;
        int col = 4 * (j & 63) + (j >> 6);
        ((__half*)(smem + OFF_B))[col * AST + k] = __float2half_rn(W_hh[i]);
    }
    __syncthreads();

    int base = blockIdx.x * NPC;
    float c[M_TILES * 8];
#pragma unroll
    for (int i = 0; i < M_TILES * 8; i++) c[i] = 0.f;

    uint32_t aoff = (uint32_t)(((lane & 15) * AST + (lane >> 4) * 8) * 2);
    uint32_t boff = (uint32_t)(((w * 64 + (lane & 7)) * AST + ((lane >> 3) & 1) * 8) * 2);

    for (int t = 0; t < DD; t++) {
        if (t) __syncthreads();
        int rb = (t - 1) & 1;
        int wb = t & 1;

        int idxL[M_TILES], idxH[M_TILES];
#pragma unroll
        for (int mi = 0; mi < M_TILES; mi++) {
            int rl = mi * 16 + rh;
            idxL[mi] = g_nbr_sorted[min(base + rl, NN - 1) * DD + t];
            idxH[mi] = g_nbr_sorted[min(base + rl + 8, NN - 1) * DD + t];
        }

#pragma unroll
        for (int nb = 0; nb < 2; nb++) {
            float d[M_TILES][4][4];
#pragma unroll
            for (int mi = 0; mi < M_TILES; mi++)
#pragma unroll
                for (int nj = 0; nj < 4; nj++)
#pragma unroll
                    for (int e = 0; e < 4; e++) d[mi][nj][e] = 0.f;

            if (t) {
                uint32_t aB = sb + OFF_A + (uint32_t)rb * ABUF + aoff;
#pragma unroll
                for (int kc = 0; kc < 64; kc += 16) {
                    uint32_t ah[M_TILES][4];
#pragma unroll
                    for (int mi = 0; mi < M_TILES; mi++)
                        ldsm4(ah[mi], aB + (uint32_t)((mi * 16 * AST + kc) * 2));
#pragma unroll
                    for (int nj = 0; nj < 4; nj++) {
                        uint32_t bh[2];
                        ldsm2(bh, sb + OFF_B + boff + (uint32_t)((((nb * 4 + nj) * 8) * AST + kc) * 2));
#pragma unroll
                        for (int mi = 0; mi < M_TILES; mi++) mma_f16(d[mi][nj], ah[mi], bh);
                    }
                }
            }

            // epilogue: paired-unit f16x2 MUFU (2.5 tanh-ops per unit)
            __half* sA = (__half*)(smem + OFF_A + (size_t)wb * ABUF);
#pragma unroll
            for (int mi = 0; mi < M_TILES; mi++) {
                float2 xL[4], xH[4];
#pragma unroll
                for (int nj = 0; nj < 4; nj++) {
                    int col = w * 64 + (nb * 4 + nj) * 8 + 2 * q;
                    xL[nj] = __ldg((const float2*)(g_Xg + (size_t)idxL[mi] * 256 + col));
                    xH[nj] = __ldg((const float2*)(g_Xg + (size_t)idxH[mi] * 256 + col));
                }
                float gI[4], gF[4], gG[4], gO[4];
#pragma unroll
                for (int nj = 0; nj < 4; nj++) {
                    float d0 = d[mi][nj][0] + xL[nj].x, d1 = d[mi][nj][1] + xL[nj].y;
                    float d2 = d[mi][nj][2] + xH[nj].x, d3 = d[mi][nj][3] + xH[nj].y;
                    float sa = (q & 1) ? d0 : d2;
                    float sbv = (q & 1) ? d1 : d3;
                    float ra = __shfl_xor_sync(0xFFFFFFFFu, sa, 1);
                    float rv = __shfl_xor_sync(0xFFFFFFFFu, sbv, 1);
                    if (q & 1) { gI[nj] = ra; gF[nj] = rv; gG[nj] = d2; gO[nj] = d3; }
                    else       { gI[nj] = d0; gF[nj] = d1; gG[nj] = ra; gO[nj] = rv; }
                }
#pragma unroll
                for (int njp = 0; njp < 2; njp++) {
                    int n0 = njp * 2, n1 = n0 + 1;
                    float2 t0 = tanh2(0.5f * gI[n0], 0.5f * gF[n0]);
                    float2 t1 = tanh2(gG[n0], 0.5f * gO[n0]);
                    float2 t2 = tanh2(0.5f * gI[n1], 0.5f * gF[n1]);
                    float2 t3 = tanh2(gG[n1], 0.5f * gO[n1]);
                    float I0 = fmaf(t0.x, 0.5f, 0.5f), F0 = fmaf(t0.y, 0.5f, 0.5f);
                    float G0 = t1.x,                   O0 = fmaf(t1.y, 0.5f, 0.5f);
                    float I1 = fmaf(t2.x, 0.5f, 0.5f), F1 = fmaf(t2.y, 0.5f, 0.5f);
                    float G1 = t3.x,                   O1 = fmaf(t3.y, 0.5f, 0.5f);
                    int c0i = mi * 8 + nb * 4 + n0;
                    int c1i = mi * 8 + nb * 4 + n1;
                    float c0 = fmaf(F0, c[c0i], I0 * G0);
                    float c1 = fmaf(F1, c[c1i], I1 * G1);
                    c[c0i] = c0; c[c1i] = c1;
                    float2 tc = tanh2(c0, c1);
                    float h0 = O0 * tc.x;
                    float h1 = O1 * tc.y;
                    int u0 = w * 16 + (nb * 4 + n0) * 2 + (q >> 1);
                    int u1 = u0 + 2;
                    int row = mi * 16 + rh + ((q & 1) ? 8 : 0);
                    sA[row * AST + u0] = __float2half_rn(h0);
                    sA[row * AST + u1] = __float2half_rn(h1);
                    if (t == DD - 1) {
                        int node = base + row;
                        if (row < NPC && node < NN) {
                            g_agg[(size_t)node * 64 + u0] = h0;
                            g_agg[(size_t)node * 64 + u1] = h1;
                        }
                    }
                }
            }
        }
    }
}

// ---------------- layer combine: h_out = relu([h_in, agg] @ Wl.T + bl), 16 nodes/blk ----------------
template <int IN_D>
__global__ void combine_kernel(const float* __restrict__ h_in, const float* __restrict__ Wl,
                               const float* __restrict__ bl, float* __restrict__ h_out) {
    constexpr int K = IN_D + 64;
    __shared__ float sWT[128 * 65];
    __shared__ float scomb[16][128];
    int tid = threadIdx.x;
    for (int i = tid; i < 64 * K; i += 256) {
        int j = i / K, k = i - j * K;
        sWT[k * 65 + j] = Wl[i];
    }
    int base = blockIdx.x * 16;
    for (int i = tid; i < 16 * IN_D; i += 256) {
        int m = i / IN_D;
        scomb[m][i - m * IN_D] = h_in[(size_t)base * IN_D + i];
    }
    for (int i = tid; i < 16 * 64; i += 256)
        scomb[i >> 6][IN_D + (i & 63)] = g_agg[(size_t)base * 64 + i];
    __syncthreads();
    int mg = tid >> 6, j = tid & 63;
#pragma unroll
    for (int mm = 0; mm < 4; mm++) {
        int m = mm * 4 + mg;
        float acc = bl[j];
#pragma unroll
        for (int k = 0; k < K; k++) acc = fmaf(scomb[m][k], sWT[k * 65 + j], acc);
        h_out[(size_t)(base + m) * 64 + j] = fmaxf(acc, 0.f);
    }
}

// ---------------- output head ----------------
__global__ void out_kernel(const float* __restrict__ h, const float* __restrict__ W_out,
                           const float* __restrict__ b_out, float* __restrict__ out) {
    int gw = (blockIdx.x * blockDim.x + threadIdx.x) >> 5;
    int lane = threadIdx.x & 31;
    if (gw >= NN) return;
    float2 hv = *(const float2*)(h + (size_t)gw * 64 + 2 * lane);
    float2 wv = *(const float2*)(W_out + 2 * lane);
    float s = hv.x * wv.x + hv.y * wv.y;
#pragma unroll
    for (int o = 16; o; o >>= 1) s += __shfl_xor_sync(0xFFFFFFFFu, s, o);
    if (lane == 0) out[gw] = s + b_out[0];
}

// ---------------- launch ----------------
extern "C" void kernel_launch(void* const* d_in, const int* in_sizes, int n_in,
                              void* d_out, int out_size) {
    (void)in_sizes; (void)n_in; (void)out_size;
    const float* nf   = (const float*)d_in[0];
    const int*   nbr  = (const int*)d_in[1];
    const float* Wout = (const float*)d_in[20];
    const float* bout = (const float*)d_in[21];
    float* out = (float*)d_out;

    float *hA = nullptr, *hB = nullptr;
    cudaGetSymbolAddress((void**)&hA, g_hA);
    cudaGetSymbolAddress((void**)&hB, g_hB);

    cudaFuncSetAttribute(lstm_mma_kernel, cudaFuncAttributeMaxDynamicSharedMemorySize, LSTM_SMEM);
    cudaFuncSetAttribute(proj_kernel<3>,  cudaFuncAttributeMaxDynamicSharedMemorySize, PROJ_SMEM);
    cudaFuncSetAttribute(proj_kernel<64>, cudaFuncAttributeMaxDynamicSharedMemorySize, PROJ_SMEM);

    sort_kernel<<<NN / 8, 256>>>(nbr);

    const float* h_in = nf;
    float* houts[3] = { hA, hB, hA };
    int lstm_grid = (NN + NPC - 1) / NPC;   // 455 <= 456 = 152*3, one wave at 3 CTAs/SM
    for (int l = 0; l < 3; l++) {
        const float* W_ih = (const float*)d_in[2 + 6 * l + 0];
        const float* W_hh = (const float*)d_in[2 + 6 * l + 1];
        const float* b_ih = (const float*)d_in[2 + 6 * l + 2];
        const float* b_hh = (const float*)d_in[2 + 6 * l + 3];
        const float* Wl   = (const float*)d_in[2 + 6 * l + 4];
        const float* bl   = (const float*)d_in[2 + 6 * l + 5];

        if (l == 0) proj_kernel<3><<<(NN + 31) / 32, 256, PROJ_SMEM>>>(h_in, W_ih, b_ih, b_hh);
        else        proj_kernel<64><<<(NN + 31) / 32, 256, PROJ_SMEM>>>(h_in, W_ih, b_ih, b_hh);
        lstm_mma_kernel<<<lstm_grid, 128, LSTM_SMEM>>>(W_hh);
        if (l == 0) combine_kernel<3><<<NN / 16, 256>>>(h_in, Wl, bl, houts[l]);
        else        combine_kernel<64><<<NN / 16, 256>>>(h_in, Wl, bl, houts[l]);
        h_in = houts[l];
    }
    out_kernel<<<NN / 8, 256>>>(h_in, Wout, bout, out);
}